// round 7
// baseline (speedup 1.0000x reference)
#include <cuda_runtime.h>
#include <cstdint>

// Problem constants
#define B_  64
#define T_  2048
#define H_  512
#define S_  512
#define K_  128
#define V_  128

#define ROWS_PER_WARP 32
#define CHUNKS_PER_B  (T_ / ROWS_PER_WARP)          // 64
#define NWARPS_TOT    (B_ * CHUNKS_PER_B)           // 4096

// Scratch (device globals — no allocation allowed)
__device__ float g_qh[B_ * H_];                 // Wh^T @ query per batch
__device__ float g_qc[B_];                      // query . bh
__device__ float g_energy[B_ * T_];             // raw energies (for attn output)
__device__ float g_pM [NWARPS_TOT];             // per-warp partial max
__device__ float g_pSA[NWARPS_TOT];             // per-warp partial sum(all exp)
__device__ float g_pSV[NWARPS_TOT];             // per-warp partial sum(valid exp)
__device__ float g_part[NWARPS_TOT * H_];       // per-warp partial weighted L sums

__device__ __forceinline__ float warp_sum(float v) {
#pragma unroll
    for (int o = 16; o; o >>= 1) v += __shfl_xor_sync(0xffffffffu, v, o);
    return v;
}
__device__ __forceinline__ float warp_max(float v) {
#pragma unroll
    for (int o = 16; o; o >>= 1) v = fmaxf(v, __shfl_xor_sync(0xffffffffu, v, o));
    return v;
}

// ---------------------------------------------------------------------------
// Kernel 1: per-batch prep.  query = ds @ Ws^T + bs ; qh = Wh^T @ query ;
// qc = query . bh.    64 blocks x 128 threads.
// ---------------------------------------------------------------------------
__global__ void k_prep(const float* __restrict__ ds,
                       const float* __restrict__ Ws,
                       const float* __restrict__ bs,
                       const float* __restrict__ Wh,
                       const float* __restrict__ bh) {
    const int b = blockIdx.x;
    const int tid = threadIdx.x;
    const int wid = tid >> 5, lane = tid & 31;

    __shared__ float s_s[S_];
    __shared__ float s_q[K_];

    for (int i = tid; i < S_; i += 128) s_s[i] = ds[b * S_ + i];
    __syncthreads();

    // query: warp-per-k (coalesced float4 reads of Ws rows)
    const float4* s4 = (const float4*)s_s;
    for (int k = wid; k < K_; k += 4) {
        const float4* w = (const float4*)(Ws + k * S_);
        float acc = 0.f;
#pragma unroll
        for (int j = 0; j < 4; j++) {
            float4 wv = w[lane + 32 * j];
            float4 sv = s4[lane + 32 * j];
            acc += wv.x * sv.x + wv.y * sv.y + wv.z * sv.z + wv.w * sv.w;
        }
        acc = warp_sum(acc);
        if (lane == 0) s_q[k] = acc + bs[k];
    }
    __syncthreads();

    // qh[h] = sum_k q_k * Wh[k,h]  (coalesced: consecutive tid -> consecutive h)
    float acc0 = 0.f, acc1 = 0.f, acc2 = 0.f, acc3 = 0.f;
    for (int k = 0; k < K_; k++) {
        const float qk = s_q[k];
        const float* whr = Wh + k * H_ + tid;
        acc0 += qk * whr[0];
        acc1 += qk * whr[128];
        acc2 += qk * whr[256];
        acc3 += qk * whr[384];
    }
    g_qh[b * H_ + tid +   0] = acc0;
    g_qh[b * H_ + tid + 128] = acc1;
    g_qh[b * H_ + tid + 256] = acc2;
    g_qh[b * H_ + tid + 384] = acc3;

    // qc = q . bh
    float p = s_q[tid] * bh[tid];
    p = warp_sum(p);
    __shared__ float s_r[4];
    if (lane == 0) s_r[wid] = p;
    __syncthreads();
    if (tid == 0) g_qc[b] = s_r[0] + s_r[1] + s_r[2] + s_r[3];
}

// ---------------------------------------------------------------------------
// Kernel 2: warp-level flash pass.  Each warp owns 32 consecutive t rows of
// one batch; streams each L row ONCE, computing the energy and immediately
// folding the row into an online-softmax-rescaled accumulator:
//   acc[h] = sum_t exp(e_t - M) * mask_t * L[b,t,h]
// plus running (M, SA = sum exp all t, SV = sum exp valid t).
// Lanes own the same H-columns they load: zero data movement between the
// dot product and the weighted accumulation.
// grid = 512 blocks x 256 threads (8 warps/block).
// ---------------------------------------------------------------------------
__global__ void __launch_bounds__(256) k_flash(const float* __restrict__ L,
                                               const int* __restrict__ lens) {
    const int w    = blockIdx.x * 8 + (threadIdx.x >> 5);  // global warp id
    const int lane = threadIdx.x & 31;
    const int b    = w >> 6;               // / CHUNKS_PER_B
    const int t0   = (w & 63) * ROWS_PER_WARP;
    const int len  = lens[b];

    // qh for this batch: 4 float4 per lane (cols lane, +32, +64, +96)
    const float4* qh4 = (const float4*)(g_qh + b * H_);
    const float4 q0 = qh4[lane +  0];
    const float4 q1 = qh4[lane + 32];
    const float4 q2 = qh4[lane + 64];
    const float4 q3 = qh4[lane + 96];
    const float  qc = g_qc[b];

    const float NEG_INF = __int_as_float(0xff800000);
    float M = NEG_INF, SA = 0.f, SV = 0.f;
    float4 a0 = make_float4(0.f, 0.f, 0.f, 0.f);
    float4 a1 = a0, a2 = a0, a3 = a0;

    const float4* Lr = (const float4*)(L + ((size_t)(b * T_ + t0)) * H_) + lane;

    for (int t = 0; t < ROWS_PER_WARP; t++) {
        const float4* row = Lr + (size_t)t * 128;
        float4 l0 = row[0];
        float4 l1 = row[32];
        float4 l2 = row[64];
        float4 l3 = row[96];

        float e = l0.x * q0.x + l0.y * q0.y + l0.z * q0.z + l0.w * q0.w
                + l1.x * q1.x + l1.y * q1.y + l1.z * q1.z + l1.w * q1.w
                + l2.x * q2.x + l2.y * q2.y + l2.z * q2.z + l2.w * q2.w
                + l3.x * q3.x + l3.y * q3.y + l3.z * q3.z + l3.w * q3.w;
        e = warp_sum(e) + qc;                   // broadcast to all lanes
        if (lane == 0) g_energy[b * T_ + t0 + t] = e;

        if (e > M) {                            // warp-uniform branch
            const float f = __expf(M - e);      // first iter: exp(-inf)=0
            SA *= f; SV *= f;
            a0.x *= f; a0.y *= f; a0.z *= f; a0.w *= f;
            a1.x *= f; a1.y *= f; a1.z *= f; a1.w *= f;
            a2.x *= f; a2.y *= f; a2.z *= f; a2.w *= f;
            a3.x *= f; a3.y *= f; a3.z *= f; a3.w *= f;
            M = e;
        }
        const float x  = __expf(e - M);
        const bool  vd = (b == 0) || (t0 + t < len);
        const float xm = vd ? x : 0.f;
        SA += x;
        SV += xm;
        a0.x += xm * l0.x; a0.y += xm * l0.y; a0.z += xm * l0.z; a0.w += xm * l0.w;
        a1.x += xm * l1.x; a1.y += xm * l1.y; a1.z += xm * l1.z; a1.w += xm * l1.w;
        a2.x += xm * l2.x; a2.y += xm * l2.y; a2.z += xm * l2.z; a2.w += xm * l2.w;
        a3.x += xm * l3.x; a3.y += xm * l3.y; a3.z += xm * l3.z; a3.w += xm * l3.w;
    }

    if (lane == 0) { g_pM[w] = M; g_pSA[w] = SA; g_pSV[w] = SV; }
    float4* P = (float4*)(g_part + (size_t)w * H_) + lane;
    P[0]  = a0;
    P[32] = a1;
    P[64] = a2;
    P[96] = a3;
}

// ---------------------------------------------------------------------------
// Kernel 3: per-batch combine + attention write + output GEMM.
//   M = max_j M_j ; scale_j = exp(M_j - M)
//   SA = sum scale_j*SA_j ; SV = sum scale_j*SV_j
//   inv = 1/max(SV, 1e-12*SA) ; A = SV*inv           (exact eps semantics)
//   ctxh[h] = inv * sum_j scale_j * part_j[h]
//   attn[b,t] = mask * exp(e_t - M) * inv
//   ctx[b,v]  = sum_h ctxh[h]*Wv[v,h] + bv[v]*A
// 64 blocks x 256 threads.
// ---------------------------------------------------------------------------
__global__ void k_final(const float* __restrict__ Wv,
                        const float* __restrict__ bv,
                        const int* __restrict__ lens,
                        float* __restrict__ ctx,
                        float* __restrict__ attn) {
    const int b = blockIdx.x;
    const int tid = threadIdx.x;
    const int wid = tid >> 5, lane = tid & 31;
    const int base = b * CHUNKS_PER_B;

    __shared__ float s_scale[CHUNKS_PER_B];
    __shared__ float s_c[H_];
    __shared__ float s_red[8];
    __shared__ float s_M, s_inv, s_A;

    // --- global max over 64 partials (warps 0 and 1) ---
    float m = (tid < CHUNKS_PER_B) ? g_pM[base + tid] : __int_as_float(0xff800000);
    if (tid < 64) {
        float wm = warp_max(m);
        if (lane == 0) s_red[tid >> 5] = wm;
    }
    __syncthreads();
    if (tid == 0) s_M = fmaxf(s_red[0], s_red[1]);
    __syncthreads();
    const float M = s_M;

    // --- scales + merged SA/SV ---
    float sa = 0.f, sv = 0.f;
    if (tid < CHUNKS_PER_B) {
        const float sc = __expf(m - M);
        s_scale[tid] = sc;
        sa = sc * g_pSA[base + tid];
        sv = sc * g_pSV[base + tid];
    }
    if (tid < 64) {
        sa = warp_sum(sa);
        sv = warp_sum(sv);
        if (lane == 0) { s_red[(tid >> 5) * 2] = sa; s_red[(tid >> 5) * 2 + 1] = sv; }
    }
    __syncthreads();
    if (tid == 0) {
        const float SA = s_red[0] + s_red[2];
        const float SV = s_red[1] + s_red[3];
        const float inv = 1.0f / fmaxf(SV, 1e-12f * SA);
        s_inv = inv;
        s_A   = SV * inv;
    }
    __syncthreads();
    const float inv = s_inv;

    // --- merge ctxh partials: thread owns h = tid and tid+256 ---
    {
        float c0 = 0.f, c1 = 0.f;
        const float* P = g_part + (size_t)base * H_;
#pragma unroll 4
        for (int j = 0; j < CHUNKS_PER_B; j++) {
            const float sc = s_scale[j];
            c0 += sc * P[j * H_ + tid];
            c1 += sc * P[j * H_ + tid + 256];
        }
        s_c[tid]       = c0 * inv;
        s_c[tid + 256] = c1 * inv;
    }

    // --- attention output (8 elements/thread) ---
    const int len = lens[b];
#pragma unroll
    for (int t = tid; t < T_; t += 256) {
        const float e = g_energy[b * T_ + t];
        const bool vd = (b == 0) || (t < len);
        attn[b * T_ + t] = vd ? __expf(e - M) * inv : 0.f;
    }
    __syncthreads();

    // --- output GEMM: warp-per-v over 128 v ---
    const float A = s_A;
    const float4* c4 = (const float4*)s_c;
    for (int v = wid; v < V_; v += 8) {
        const float4* w4 = (const float4*)(Wv + v * H_);
        float acc = 0.f;
#pragma unroll
        for (int j = 0; j < 4; j++) {
            float4 wv = w4[lane + 32 * j];
            float4 cv = c4[lane + 32 * j];
            acc += wv.x * cv.x + wv.y * cv.y + wv.z * cv.z + wv.w * cv.w;
        }
        acc = warp_sum(acc);
        if (lane == 0) ctx[b * V_ + v] = acc + bv[v] * A;
    }
}

// ---------------------------------------------------------------------------
extern "C" void kernel_launch(void* const* d_in, const int* in_sizes, int n_in,
                              void* d_out, int out_size) {
    const float* ds   = (const float*)d_in[0];  // decoder_state (B,S)
    const float* L    = (const float*)d_in[1];  // listener_output (B,T,H)
    const int*   lens = (const int*)  d_in[2];  // outputs_length (B,)
    const float* Ws   = (const float*)d_in[3];
    const float* bs   = (const float*)d_in[4];
    const float* Wh   = (const float*)d_in[5];
    const float* bh   = (const float*)d_in[6];
    const float* Wv   = (const float*)d_in[7];
    const float* bv   = (const float*)d_in[8];

    float* ctx  = (float*)d_out;            // (B,V)   = 8192 floats
    float* attn = ctx + B_ * V_;            // (B,1,T) = 131072 floats

    k_prep <<<B_, 128>>>(ds, Ws, bs, Wh, bh);
    k_flash<<<NWARPS_TOT / 8, 256>>>(L, lens);
    k_final<<<B_, 256>>>(Wv, bv, lens, ctx, attn);
}

// round 8
// speedup vs baseline: 1.4177x; 1.4177x over previous
#include <cuda_runtime.h>
#include <cstdint>

// Problem constants
#define B_  64
#define T_  2048
#define H_  512
#define S_  512
#define K_  128
#define V_  128

#define ROWS_PER_WARP 32
#define CHUNKS_PER_B  (T_ / ROWS_PER_WARP)          // 64
#define NWARPS_TOT    (B_ * CHUNKS_PER_B)           // 4096

// Scratch (device globals — no allocation allowed)
__device__ float g_q [B_ * K_];                 // query = ds@Ws^T + bs
__device__ float g_qh[B_ * H_];                 // Wh^T @ query per batch
__device__ float g_qc[B_];                      // query . bh
__device__ float g_energy[B_ * T_];             // raw energies (for attn output)
__device__ float g_pM [NWARPS_TOT];             // per-warp partial max
__device__ float g_pSA[NWARPS_TOT];             // per-warp partial sum(all exp)
__device__ float g_pSV[NWARPS_TOT];             // per-warp partial sum(valid exp)
__device__ float g_part[NWARPS_TOT * H_];       // per-warp partial weighted L sums

__device__ __forceinline__ float warp_sum(float v) {
#pragma unroll
    for (int o = 16; o; o >>= 1) v += __shfl_xor_sync(0xffffffffu, v, o);
    return v;
}
__device__ __forceinline__ float warp_max(float v) {
#pragma unroll
    for (int o = 16; o; o >>= 1) v = fmaxf(v, __shfl_xor_sync(0xffffffffu, v, o));
    return v;
}

// ---------------------------------------------------------------------------
// Kernel 1a: query[b,k] = ds[b] . Ws[k] + bs[k].  Warp per (b,k):
// 8192 warps = 1024 blocks x 256 threads.  Latency fully overlapped.
// ---------------------------------------------------------------------------
__global__ void __launch_bounds__(256) k_query(const float* __restrict__ ds,
                                               const float* __restrict__ Ws,
                                               const float* __restrict__ bs) {
    const int w    = blockIdx.x * 8 + (threadIdx.x >> 5);  // 0..8191
    const int lane = threadIdx.x & 31;
    const int b = w >> 7;          // / K_
    const int k = w & (K_ - 1);

    const float4* d4 = (const float4*)(ds + b * S_);
    const float4* w4 = (const float4*)(Ws + k * S_);
    float acc = 0.f;
#pragma unroll
    for (int j = 0; j < 4; j++) {
        float4 dv = d4[lane + 32 * j];
        float4 wv = w4[lane + 32 * j];
        acc += dv.x * wv.x + dv.y * wv.y + dv.z * wv.z + dv.w * wv.w;
    }
    acc = warp_sum(acc);
    if (lane == 0) g_q[b * K_ + k] = acc + bs[k];
}

// ---------------------------------------------------------------------------
// Kernel 1b: qh[b,h] = sum_k q[b,k] * Wh[k,h]  (thread per (b,h); coalesced
// Wh columns, uniform q broadcast).  Also qc[b] = q[b] . bh (warp 0 of the
// even blocks).  128 blocks x 256 threads.
// ---------------------------------------------------------------------------
__global__ void __launch_bounds__(256) k_qh(const float* __restrict__ Wh,
                                            const float* __restrict__ bh) {
    const int tid = threadIdx.x;
    const int idx = blockIdx.x * 256 + tid;   // 0..32767
    const int b = idx >> 9;                    // / H_
    const int h = idx & (H_ - 1);

    const float* q = g_q + b * K_;
    const float* whc = Wh + h;
    float acc = 0.f;
#pragma unroll 8
    for (int k = 0; k < K_; k++)
        acc += q[k] * whc[k * H_];
    g_qh[b * H_ + h] = acc;

    // qc for this batch (one warp, even blocks handle h-chunk [0,256))
    if ((blockIdx.x & 1) == 0 && tid < 32) {
        float4 qv  = ((const float4*)q)[tid];
        float4 bhv = ((const float4*)bh)[tid];
        float p = qv.x * bhv.x + qv.y * bhv.y + qv.z * bhv.z + qv.w * bhv.w;
        p = warp_sum(p);
        if (tid == 0) g_qc[b] = p;
    }
}

// ---------------------------------------------------------------------------
// Kernel 2: warp-level flash pass.  Each warp owns 32 consecutive t rows of
// one batch; streams each L row ONCE, computing the energy and immediately
// folding the row into an online-softmax-rescaled accumulator:
//   acc[h] = sum_t exp(e_t - M) * mask_t * L[b,t,h]
// plus running (M, SA = sum exp all t, SV = sum exp valid t).
// grid = 512 blocks x 256 threads (8 warps/block).
// ---------------------------------------------------------------------------
__global__ void __launch_bounds__(256) k_flash(const float* __restrict__ L,
                                               const int* __restrict__ lens) {
    const int w    = blockIdx.x * 8 + (threadIdx.x >> 5);  // global warp id
    const int lane = threadIdx.x & 31;
    const int b    = w >> 6;               // / CHUNKS_PER_B
    const int t0   = (w & 63) * ROWS_PER_WARP;
    const int len  = lens[b];
    const int nv   = (b == 0) ? ROWS_PER_WARP
                              : min(max(len - t0, 0), ROWS_PER_WARP);

    const float4* qh4 = (const float4*)(g_qh + b * H_);
    const float4 q0 = qh4[lane +  0];
    const float4 q1 = qh4[lane + 32];
    const float4 q2 = qh4[lane + 64];
    const float4 q3 = qh4[lane + 96];
    const float  qc = g_qc[b];

    const float NEG_INF = __int_as_float(0xff800000);
    float M = NEG_INF, SA = 0.f, SV = 0.f;
    float4 a0 = make_float4(0.f, 0.f, 0.f, 0.f);
    float4 a1 = a0, a2 = a0, a3 = a0;

    const float4* Lr = (const float4*)(L + ((size_t)(b * T_ + t0)) * H_) + lane;

    for (int t = 0; t < ROWS_PER_WARP; t++) {
        const float4* row = Lr + (size_t)t * 128;
        float4 l0 = row[0];
        float4 l1 = row[32];
        float4 l2 = row[64];
        float4 l3 = row[96];

        float e = l0.x * q0.x + l0.y * q0.y + l0.z * q0.z + l0.w * q0.w
                + l1.x * q1.x + l1.y * q1.y + l1.z * q1.z + l1.w * q1.w
                + l2.x * q2.x + l2.y * q2.y + l2.z * q2.z + l2.w * q2.w
                + l3.x * q3.x + l3.y * q3.y + l3.z * q3.z + l3.w * q3.w;
        e = warp_sum(e) + qc;                   // broadcast to all lanes
        if (lane == 0) g_energy[b * T_ + t0 + t] = e;

        if (e > M) {                            // warp-uniform branch
            const float f = __expf(M - e);      // first iter: exp(-inf)=0
            SA *= f; SV *= f;
            a0.x *= f; a0.y *= f; a0.z *= f; a0.w *= f;
            a1.x *= f; a1.y *= f; a1.z *= f; a1.w *= f;
            a2.x *= f; a2.y *= f; a2.z *= f; a2.w *= f;
            a3.x *= f; a3.y *= f; a3.z *= f; a3.w *= f;
            M = e;
        }
        const float x  = __expf(e - M);
        const float xm = (t < nv) ? x : 0.f;
        SA += x;
        SV += xm;
        a0.x += xm * l0.x; a0.y += xm * l0.y; a0.z += xm * l0.z; a0.w += xm * l0.w;
        a1.x += xm * l1.x; a1.y += xm * l1.y; a1.z += xm * l1.z; a1.w += xm * l1.w;
        a2.x += xm * l2.x; a2.y += xm * l2.y; a2.z += xm * l2.z; a2.w += xm * l2.w;
        a3.x += xm * l3.x; a3.y += xm * l3.y; a3.z += xm * l3.z; a3.w += xm * l3.w;
    }

    if (lane == 0) { g_pM[w] = M; g_pSA[w] = SA; g_pSV[w] = SV; }
    float4* P = (float4*)(g_part + (size_t)w * H_) + lane;
    P[0]  = a0;
    P[32] = a1;
    P[64] = a2;
    P[96] = a3;
}

// ---------------------------------------------------------------------------
// Kernel 3: per-batch combine + attention write + output GEMM.
//   M = max_j M_j ; scale_j = exp(M_j - M)
//   SA = sum scale_j*SA_j ; SV = sum scale_j*SV_j
//   inv = 1/max(SV, 1e-12*SA) ; A = SV*inv           (exact eps semantics)
//   ctxh[h] = inv * sum_j scale_j * part_j[h]
//   attn[b,t] = mask * exp(e_t - M) * inv
//   ctx[b,v]  = sum_h ctxh[h]*Wv[v,h] + bv[v]*A
// 64 blocks x 256 threads.
// ---------------------------------------------------------------------------
__global__ void k_final(const float* __restrict__ Wv,
                        const float* __restrict__ bv,
                        const int* __restrict__ lens,
                        float* __restrict__ ctx,
                        float* __restrict__ attn) {
    const int b = blockIdx.x;
    const int tid = threadIdx.x;
    const int wid = tid >> 5, lane = tid & 31;
    const int base = b * CHUNKS_PER_B;

    __shared__ float s_scale[CHUNKS_PER_B];
    __shared__ float s_c[H_];
    __shared__ float s_red[8];
    __shared__ float s_M, s_inv, s_A;

    // --- global max over 64 partials (warps 0 and 1) ---
    float m = (tid < CHUNKS_PER_B) ? g_pM[base + tid] : __int_as_float(0xff800000);
    if (tid < 64) {
        float wm = warp_max(m);
        if (lane == 0) s_red[tid >> 5] = wm;
    }
    __syncthreads();
    if (tid == 0) s_M = fmaxf(s_red[0], s_red[1]);
    __syncthreads();
    const float M = s_M;

    // --- scales + merged SA/SV ---
    float sa = 0.f, sv = 0.f;
    if (tid < CHUNKS_PER_B) {
        const float sc = __expf(m - M);
        s_scale[tid] = sc;
        sa = sc * g_pSA[base + tid];
        sv = sc * g_pSV[base + tid];
    }
    if (tid < 64) {
        sa = warp_sum(sa);
        sv = warp_sum(sv);
        if (lane == 0) { s_red[(tid >> 5) * 2] = sa; s_red[(tid >> 5) * 2 + 1] = sv; }
    }
    __syncthreads();
    if (tid == 0) {
        const float SA = s_red[0] + s_red[2];
        const float SV = s_red[1] + s_red[3];
        const float inv = 1.0f / fmaxf(SV, 1e-12f * SA);
        s_inv = inv;
        s_A   = SV * inv;
    }
    __syncthreads();
    const float inv = s_inv;

    // --- merge ctxh partials: thread owns h = tid and tid+256 ---
    {
        float c0 = 0.f, c1 = 0.f;
        const float* P = g_part + (size_t)base * H_;
#pragma unroll 4
        for (int j = 0; j < CHUNKS_PER_B; j++) {
            const float sc = s_scale[j];
            c0 += sc * P[j * H_ + tid];
            c1 += sc * P[j * H_ + tid + 256];
        }
        s_c[tid]       = c0 * inv;
        s_c[tid + 256] = c1 * inv;
    }

    // --- attention output (8 elements/thread) ---
    const int len = lens[b];
#pragma unroll
    for (int t = tid; t < T_; t += 256) {
        const float e = g_energy[b * T_ + t];
        const bool vd = (b == 0) || (t < len);
        attn[b * T_ + t] = vd ? __expf(e - M) * inv : 0.f;
    }
    __syncthreads();

    // --- output GEMM: warp-per-v over 128 v ---
    const float A = s_A;
    const float4* c4 = (const float4*)s_c;
    for (int v = wid; v < V_; v += 8) {
        const float4* w4 = (const float4*)(Wv + v * H_);
        float acc = 0.f;
#pragma unroll
        for (int j = 0; j < 4; j++) {
            float4 wv = w4[lane + 32 * j];
            float4 cv = c4[lane + 32 * j];
            acc += wv.x * cv.x + wv.y * cv.y + wv.z * cv.z + wv.w * cv.w;
        }
        acc = warp_sum(acc);
        if (lane == 0) ctx[b * V_ + v] = acc + bv[v] * A;
    }
}

// ---------------------------------------------------------------------------
extern "C" void kernel_launch(void* const* d_in, const int* in_sizes, int n_in,
                              void* d_out, int out_size) {
    const float* ds   = (const float*)d_in[0];  // decoder_state (B,S)
    const float* L    = (const float*)d_in[1];  // listener_output (B,T,H)
    const int*   lens = (const int*)  d_in[2];  // outputs_length (B,)
    const float* Ws   = (const float*)d_in[3];
    const float* bs   = (const float*)d_in[4];
    const float* Wh   = (const float*)d_in[5];
    const float* bh   = (const float*)d_in[6];
    const float* Wv   = (const float*)d_in[7];
    const float* bv   = (const float*)d_in[8];

    float* ctx  = (float*)d_out;            // (B,V)   = 8192 floats
    float* attn = ctx + B_ * V_;            // (B,1,T) = 131072 floats

    k_query<<<(B_ * K_) / 8, 256>>>(ds, Ws, bs);
    k_qh   <<<(B_ * H_) / 256, 256>>>(Wh, bh);
    k_flash<<<NWARPS_TOT / 8, 256>>>(L, lens);
    k_final<<<B_, 256>>>(Wv, bv, lens, ctx, attn);
}

// round 10
// speedup vs baseline: 1.5701x; 1.1075x over previous
#include <cuda_runtime.h>
#include <cstdint>

// Problem constants
#define B_  64
#define T_  2048
#define H_  512
#define S_  512
#define K_  128
#define V_  128

#define ROWS_PER_WARP 16
#define CHUNKS_PER_B  (T_ / ROWS_PER_WARP)          // 128
#define NWARPS_TOT    (B_ * CHUNKS_PER_B)           // 8192

// Scratch (device globals — no allocation allowed)
__device__ float g_q [B_ * K_];                 // query = ds@Ws^T + bs
__device__ float g_qh[B_ * H_];                 // Wh^T @ query per batch
__device__ float g_qc[B_];                      // query . bh
__device__ float g_energy[B_ * T_];             // raw energies
__device__ float g_pM [NWARPS_TOT];             // per-warp partial max
__device__ float g_pSA[NWARPS_TOT];             // per-warp partial sum(all exp)
__device__ float g_pSV[NWARPS_TOT];             // per-warp partial sum(valid exp)
__device__ float g_scale[NWARPS_TOT];           // exp(pM - M_b)
__device__ float g_part[NWARPS_TOT * H_];       // per-warp partial weighted L sums (16 MB)
__device__ float g_ctxh[B_ * H_];               // merged, inv-scaled context in H
__device__ float g_M[B_], g_inv[B_], g_A[B_];   // per-batch softmax stats

__device__ __forceinline__ float warp_sum(float v) {
#pragma unroll
    for (int o = 16; o; o >>= 1) v += __shfl_xor_sync(0xffffffffu, v, o);
    return v;
}
__device__ __forceinline__ void warp_sum2(float& a, float& b) {
#pragma unroll
    for (int o = 16; o; o >>= 1) {
        a += __shfl_xor_sync(0xffffffffu, a, o);
        b += __shfl_xor_sync(0xffffffffu, b, o);
    }
}
__device__ __forceinline__ float warp_max(float v) {
#pragma unroll
    for (int o = 16; o; o >>= 1) v = fmaxf(v, __shfl_xor_sync(0xffffffffu, v, o));
    return v;
}

// ---------------------------------------------------------------------------
// Kernel 1a: query[b,k] = ds[b] . Ws[k] + bs[k].  Warp per (b,k).
// ---------------------------------------------------------------------------
__global__ void __launch_bounds__(256) k_query(const float* __restrict__ ds,
                                               const float* __restrict__ Ws,
                                               const float* __restrict__ bs) {
    const int w    = blockIdx.x * 8 + (threadIdx.x >> 5);
    const int lane = threadIdx.x & 31;
    const int b = w >> 7;
    const int k = w & (K_ - 1);

    const float4* d4 = (const float4*)(ds + b * S_);
    const float4* w4 = (const float4*)(Ws + k * S_);
    float acc = 0.f;
#pragma unroll
    for (int j = 0; j < 4; j++) {
        float4 dv = d4[lane + 32 * j];
        float4 wv = w4[lane + 32 * j];
        acc += dv.x * wv.x + dv.y * wv.y + dv.z * wv.z + dv.w * wv.w;
    }
    acc = warp_sum(acc);
    if (lane == 0) g_q[b * K_ + k] = acc + bs[k];
}

// ---------------------------------------------------------------------------
// Kernel 1b: qh[b,h] = sum_k q[b,k]*Wh[k,h] (thread per (b,h)); qc folded in.
// ---------------------------------------------------------------------------
__global__ void __launch_bounds__(256) k_qh(const float* __restrict__ Wh,
                                            const float* __restrict__ bh) {
    const int tid = threadIdx.x;
    const int idx = blockIdx.x * 256 + tid;
    const int b = idx >> 9;
    const int h = idx & (H_ - 1);

    const float* q = g_q + b * K_;
    const float* whc = Wh + h;
    float acc = 0.f;
#pragma unroll 8
    for (int k = 0; k < K_; k++)
        acc += q[k] * whc[k * H_];
    g_qh[b * H_ + h] = acc;

    if ((blockIdx.x & 1) == 0 && tid < 32) {
        float4 qv  = ((const float4*)q)[tid];
        float4 bhv = ((const float4*)bh)[tid];
        float p = qv.x * bhv.x + qv.y * bhv.y + qv.z * bhv.z + qv.w * bhv.w;
        p = warp_sum(p);
        if (tid == 0) g_qc[b] = p;
    }
}

// ---------------------------------------------------------------------------
// Kernel 2: warp-level flash pass, 16 t-rows per warp, processed in PAIRS
// (two independent dot/shfl chains interleave; one rescale check per pair).
// 8192 warps = 1024 blocks x 256 threads.  Streams L exactly once.
// ---------------------------------------------------------------------------
__global__ void __launch_bounds__(256) k_flash(const float* __restrict__ L,
                                               const int* __restrict__ lens) {
    const int w    = blockIdx.x * 8 + (threadIdx.x >> 5);
    const int lane = threadIdx.x & 31;
    const int b    = w >> 7;                       // / CHUNKS_PER_B
    const int t0   = (w & (CHUNKS_PER_B - 1)) * ROWS_PER_WARP;
    const int len  = lens[b];
    const int nv   = (b == 0) ? ROWS_PER_WARP
                              : min(max(len - t0, 0), ROWS_PER_WARP);

    const float4* qh4 = (const float4*)(g_qh + b * H_);
    const float4 q0 = qh4[lane +  0];
    const float4 q1 = qh4[lane + 32];
    const float4 q2 = qh4[lane + 64];
    const float4 q3 = qh4[lane + 96];
    const float  qc = g_qc[b];

    float M = __int_as_float(0xff800000), SA = 0.f, SV = 0.f;
    float4 a0 = make_float4(0.f, 0.f, 0.f, 0.f);
    float4 a1 = a0, a2 = a0, a3 = a0;

    const float4* Lr = (const float4*)(L + ((size_t)(b * T_ + t0)) * H_) + lane;

#pragma unroll 2
    for (int t = 0; t < ROWS_PER_WARP; t += 2) {
        const float4* rowA = Lr + (size_t)t * 128;
        const float4* rowB = rowA + 128;
        float4 la0 = rowA[0],  la1 = rowA[32], la2 = rowA[64], la3 = rowA[96];
        float4 lb0 = rowB[0],  lb1 = rowB[32], lb2 = rowB[64], lb3 = rowB[96];

        float eA = la0.x * q0.x + la0.y * q0.y + la0.z * q0.z + la0.w * q0.w
                 + la1.x * q1.x + la1.y * q1.y + la1.z * q1.z + la1.w * q1.w
                 + la2.x * q2.x + la2.y * q2.y + la2.z * q2.z + la2.w * q2.w
                 + la3.x * q3.x + la3.y * q3.y + la3.z * q3.z + la3.w * q3.w;
        float eB = lb0.x * q0.x + lb0.y * q0.y + lb0.z * q0.z + lb0.w * q0.w
                 + lb1.x * q1.x + lb1.y * q1.y + lb1.z * q1.z + lb1.w * q1.w
                 + lb2.x * q2.x + lb2.y * q2.y + lb2.z * q2.z + lb2.w * q2.w
                 + lb3.x * q3.x + lb3.y * q3.y + lb3.z * q3.z + lb3.w * q3.w;
        warp_sum2(eA, eB);                       // two interleaved chains
        eA += qc; eB += qc;
        if (lane == 0) {
            g_energy[b * T_ + t0 + t]     = eA;
            g_energy[b * T_ + t0 + t + 1] = eB;
        }

        const float mN = fmaxf(M, fmaxf(eA, eB));
        if (mN > M) {                            // warp-uniform
            const float f = __expf(M - mN);      // first pair: exp(-inf)=0
            SA *= f; SV *= f;
            a0.x *= f; a0.y *= f; a0.z *= f; a0.w *= f;
            a1.x *= f; a1.y *= f; a1.z *= f; a1.w *= f;
            a2.x *= f; a2.y *= f; a2.z *= f; a2.w *= f;
            a3.x *= f; a3.y *= f; a3.z *= f; a3.w *= f;
            M = mN;
        }
        const float xA = __expf(eA - M);
        const float xB = __expf(eB - M);
        const float xmA = (t     < nv) ? xA : 0.f;
        const float xmB = (t + 1 < nv) ? xB : 0.f;
        SA += xA + xB;
        SV += xmA + xmB;
        a0.x += xmA * la0.x + xmB * lb0.x;  a0.y += xmA * la0.y + xmB * lb0.y;
        a0.z += xmA * la0.z + xmB * lb0.z;  a0.w += xmA * la0.w + xmB * lb0.w;
        a1.x += xmA * la1.x + xmB * lb1.x;  a1.y += xmA * la1.y + xmB * lb1.y;
        a1.z += xmA * la1.z + xmB * lb1.z;  a1.w += xmA * la1.w + xmB * lb1.w;
        a2.x += xmA * la2.x + xmB * lb2.x;  a2.y += xmA * la2.y + xmB * lb2.y;
        a2.z += xmA * la2.z + xmB * lb2.z;  a2.w += xmA * la2.w + xmB * lb2.w;
        a3.x += xmA * la3.x + xmB * lb3.x;  a3.y += xmA * la3.y + xmB * lb3.y;
        a3.z += xmA * la3.z + xmB * lb3.z;  a3.w += xmA * la3.w + xmB * lb3.w;
    }

    if (lane == 0) { g_pM[w] = M; g_pSA[w] = SA; g_pSV[w] = SV; }
    float4* P = (float4*)(g_part + (size_t)w * H_) + lane;
    P[0]  = a0;
    P[32] = a1;
    P[64] = a2;
    P[96] = a3;
}

// ---------------------------------------------------------------------------
// Kernel 3a: per-batch scalar merge.  M_b, scale_j, inv, A.  64 x 128.
// ---------------------------------------------------------------------------
__global__ void k_reduceMS(void) {
    const int b = blockIdx.x;
    const int tid = threadIdx.x;            // 0..127
    const int base = b * CHUNKS_PER_B;

    __shared__ float s_red[8];
    const float m = g_pM[base + tid];
    float wm = warp_max(m);
    if ((tid & 31) == 0) s_red[tid >> 5] = wm;
    __syncthreads();
    if (tid == 0)
        s_red[4] = fmaxf(fmaxf(s_red[0], s_red[1]), fmaxf(s_red[2], s_red[3]));
    __syncthreads();
    const float M = s_red[4];

    const float sc = __expf(m - M);
    g_scale[base + tid] = sc;
    float sa = sc * g_pSA[base + tid];
    float sv = sc * g_pSV[base + tid];
    warp_sum2(sa, sv);
    __shared__ float sA[4], sV[4];
    if ((tid & 31) == 0) { sA[tid >> 5] = sa; sV[tid >> 5] = sv; }
    __syncthreads();
    if (tid == 0) {
        const float SA = sA[0] + sA[1] + sA[2] + sA[3];
        const float SV = sV[0] + sV[1] + sV[2] + sV[3];
        const float inv = 1.0f / fmaxf(SV, 1e-12f * SA);
        g_M[b]   = M;
        g_inv[b] = inv;
        g_A[b]   = SV * inv;
    }
}

// ---------------------------------------------------------------------------
// Kernel 3b: merge partials: ctxh[b,h] = inv * sum_j scale_j * part[j,h].
// Thread per (b,h): 128 blocks x 256, coalesced in h.
// ---------------------------------------------------------------------------
__global__ void __launch_bounds__(256) k_merge(void) {
    const int idx = blockIdx.x * 256 + threadIdx.x;   // 0..32767
    const int b = idx >> 9;
    const int h = idx & (H_ - 1);
    const int base = b * CHUNKS_PER_B;

    const float* P  = g_part + (size_t)base * H_ + h;
    const float* SC = g_scale + base;
    float acc = 0.f;
#pragma unroll 8
    for (int j = 0; j < CHUNKS_PER_B; j++)
        acc += SC[j] * P[(size_t)j * H_];
    g_ctxh[b * H_ + h] = acc * g_inv[b];
}

// ---------------------------------------------------------------------------
// Kernel 3c: attention output.  Thread per (b,t): 512 blocks x 256.
// ---------------------------------------------------------------------------
__global__ void __launch_bounds__(256) k_attn(const int* __restrict__ lens,
                                              float* __restrict__ attn) {
    const int idx = blockIdx.x * 256 + threadIdx.x;   // 0..131071
    const int b = idx >> 11;
    const int t = idx & (T_ - 1);
    const bool vd = (b == 0) || (t < lens[b]);
    attn[idx] = vd ? __expf(g_energy[idx] - g_M[b]) * g_inv[b] : 0.f;
}

// ---------------------------------------------------------------------------
// Kernel 3d: output GEMM.  Warp per (b,v): 1024 blocks x 256.
//   ctx[b,v] = sum_h ctxh[b,h]*Wv[v,h] + bv[v]*A[b]
// ---------------------------------------------------------------------------
__global__ void __launch_bounds__(256) k_out(const float* __restrict__ Wv,
                                             const float* __restrict__ bv,
                                             float* __restrict__ ctx) {
    const int w    = blockIdx.x * 8 + (threadIdx.x >> 5);  // 0..8191
    const int lane = threadIdx.x & 31;
    const int b = w >> 7;
    const int v = w & (V_ - 1);

    const float4* c4 = (const float4*)(g_ctxh + b * H_);
    const float4* w4 = (const float4*)(Wv + v * H_);
    float acc = 0.f;
#pragma unroll
    for (int j = 0; j < 4; j++) {
        float4 wv = w4[lane + 32 * j];
        float4 cv = c4[lane + 32 * j];
        acc += wv.x * cv.x + wv.y * cv.y + wv.z * cv.z + wv.w * cv.w;
    }
    acc = warp_sum(acc);
    if (lane == 0) ctx[b * V_ + v] = acc + bv[v] * g_A[b];
}

// ---------------------------------------------------------------------------
extern "C" void kernel_launch(void* const* d_in, const int* in_sizes, int n_in,
                              void* d_out, int out_size) {
    const float* ds   = (const float*)d_in[0];  // decoder_state (B,S)
    const float* L    = (const float*)d_in[1];  // listener_output (B,T,H)
    const int*   lens = (const int*)  d_in[2];  // outputs_length (B,)
    const float* Ws   = (const float*)d_in[3];
    const float* bs   = (const float*)d_in[4];
    const float* Wh   = (const float*)d_in[5];
    const float* bh   = (const float*)d_in[6];
    const float* Wv   = (const float*)d_in[7];
    const float* bv   = (const float*)d_in[8];

    float* ctx  = (float*)d_out;            // (B,V)   = 8192 floats
    float* attn = ctx + B_ * V_;            // (B,1,T) = 131072 floats

    k_query   <<<(B_ * K_) / 8, 256>>>(ds, Ws, bs);
    k_qh      <<<(B_ * H_) / 256, 256>>>(Wh, bh);
    k_flash   <<<NWARPS_TOT / 8, 256>>>(L, lens);
    k_reduceMS<<<B_, 128>>>();
    k_merge   <<<(B_ * H_) / 256, 256>>>();
    k_attn    <<<(B_ * T_) / 256, 256>>>(lens, attn);
    k_out     <<<(B_ * V_) / 8, 256>>>(Wv, bv, ctx);
}